// round 5
// baseline (speedup 1.0000x reference)
#include <cuda_runtime.h>
#include <cuda_bf16.h>

// img : (1, 64, 64, 1024) float32, NHWC
// rois: (1, 512, 4) int32  -> (x, y, w, h)
// out : (1, 512, 7, 7, 1024) float32
#define POOL   7
#define NROIS  512
#define IMG_W  64

// One CTA per (roi, py) output row: 7 cells, 256 threads, 1 float4 lane each.
// No software pipeline: minimal registers (<=32 via launch_bounds) so 8 CTAs
// = 64 warps are resident per SM. Latency is hidden by warp count; steady
// state should saturate the L1 wavefront pipe (~20 wf per warp-iteration).
__global__ __launch_bounds__(256, 8)
void roi_pool_kernel(const float* __restrict__ img,
                     const int*   __restrict__ rois,
                     float*       __restrict__ out)
{
    const int bid = blockIdx.x;           // roi*7 + py
    const int roi = bid / POOL;
    const int py  = bid - roi * POOL;

    const int4 r = __ldg(((const int4*)rois) + roi);   // x, y, w, h

    // Loop-invariant y-axis work (match reference fp32 arithmetic exactly)
    const float stepx = (float)r.z / (float)POOL;
    const float sy = (float)py * ((float)r.w / (float)POOL);
    const int   y0 = (int)sy;
    const float fy = sy - (float)y0;
    const int   y1 = min(y0 + 1, r.w - 1);

    const int c = threadIdx.x;            // 0..255 float4 lane
    const float4* ibase = (const float4*)img;
    const unsigned row0 = (unsigned)((r.y + y0) * IMG_W + r.x) * 256u + c;
    const unsigned row1 = (unsigned)((r.y + y1) * IMG_W + r.x) * 256u + c;
    const int wm1 = r.z - 1;

    float4* optr = (float4*)out + ((size_t)bid * POOL) * 256 + c;

    #pragma unroll
    for (int px = 0; px < POOL; ++px) {
        const float sx = (float)px * stepx;
        const int   x0 = (int)sx;
        const float fx = sx - (float)x0;
        const int   x1 = min(x0 + 1, wm1);

        // 4 independent 16B loads, back-to-back.
        const float4 v00 = __ldg(ibase + row0 + (unsigned)x0 * 256u);
        const float4 v01 = __ldg(ibase + row0 + (unsigned)x1 * 256u);
        const float4 v10 = __ldg(ibase + row1 + (unsigned)x0 * 256u);
        const float4 v11 = __ldg(ibase + row1 + (unsigned)x1 * 256u);

        const float w11 = fx * fy;
        const float w01 = fx - w11;          // fx*(1-fy)
        const float w10 = fy - w11;          // (1-fx)*fy
        const float w00 = 1.0f - fx - w10;   // (1-fx)*(1-fy)

        float4 o;
        o.x = fmaf(v11.x, w11, fmaf(v10.x, w10, fmaf(v01.x, w01, v00.x * w00)));
        o.y = fmaf(v11.y, w11, fmaf(v10.y, w10, fmaf(v01.y, w01, v00.y * w00)));
        o.z = fmaf(v11.z, w11, fmaf(v10.z, w10, fmaf(v01.z, w01, v00.z * w00)));
        o.w = fmaf(v11.w, w11, fmaf(v10.w, w10, fmaf(v01.w, w01, v00.w * w00)));

        *optr = o;
        optr += 256;
    }
}

extern "C" void kernel_launch(void* const* d_in, const int* in_sizes, int n_in,
                              void* d_out, int out_size)
{
    const float* img  = (const float*)d_in[0];
    const int*   rois = (const int*)d_in[1];
    float*       out  = (float*)d_out;

    const int grid = NROIS * POOL;        // 3584 CTAs, one per (roi, py)
    roi_pool_kernel<<<grid, 256>>>(img, rois, out);
}

// round 6
// speedup vs baseline: 1.4600x; 1.4600x over previous
#include <cuda_runtime.h>
#include <cuda_bf16.h>

// img : (1, 64, 64, 1024) float32, NHWC
// rois: (1, 512, 4) int32  -> (x, y, w, h)
// out : (1, 512, 7, 7, 1024) float32
#define POOL   7
#define NROIS  512
#define IMG_W  64

// Packed f32x2 helpers (sm_103a): one instruction processes 2 floats.
__device__ __forceinline__ unsigned long long pk(float lo, float hi) {
    unsigned long long r;
    asm("mov.b64 %0, {%1, %2};" : "=l"(r) : "f"(lo), "f"(hi));
    return r;
}
__device__ __forceinline__ unsigned long long mul2(unsigned long long a, unsigned long long b) {
    unsigned long long r;
    asm("mul.rn.f32x2 %0, %1, %2;" : "=l"(r) : "l"(a), "l"(b));
    return r;
}
__device__ __forceinline__ unsigned long long fma2(unsigned long long a, unsigned long long b,
                                                   unsigned long long c) {
    unsigned long long r;
    asm("fma.rn.f32x2 %0, %1, %2, %3;" : "=l"(r) : "l"(a), "l"(b), "l"(c));
    return r;
}

// Blend one 16B chunk (2x b64) with packed weights.
__device__ __forceinline__ ulonglong2 blend2(ulonglong2 v00, ulonglong2 v01,
                                             ulonglong2 v10, ulonglong2 v11,
                                             unsigned long long W00, unsigned long long W01,
                                             unsigned long long W10, unsigned long long W11) {
    ulonglong2 o;
    o.x = fma2(v11.x, W11, fma2(v10.x, W10, fma2(v01.x, W01, mul2(v00.x, W00))));
    o.y = fma2(v11.y, W11, fma2(v10.y, W10, fma2(v01.y, W01, mul2(v00.y, W00))));
    return o;
}

// One CTA per (roi, py) output row: 7 cells. 128 threads, each owning 2 of the
// 256 float4 lanes (c and c+128) -> 8 independent 16B loads in flight per
// thread per cell. Bilinear math in packed f32x2 (half the FFMA issue slots).
__global__ __launch_bounds__(128)
void roi_pool_kernel(const float* __restrict__ img,
                     const int*   __restrict__ rois,
                     float*       __restrict__ out)
{
    const int bid = blockIdx.x;           // roi*7 + py
    const int roi = bid / POOL;
    const int py  = bid - roi * POOL;

    const int4 r = __ldg(((const int4*)rois) + roi);   // x, y, w, h

    // Loop-invariant y-axis work (match reference fp32 arithmetic exactly)
    const float stepx = (float)r.z / (float)POOL;
    const float sy = (float)py * ((float)r.w / (float)POOL);
    const int   y0 = (int)sy;
    const float fy = sy - (float)y0;
    const int   y1 = min(y0 + 1, r.w - 1);
    const int   wm1 = r.z - 1;

    const int c0 = threadIdx.x;           // 0..127
    const int c1 = c0 + 128;              // 128..255

    const ulonglong2* ibase = (const ulonglong2*)img;  // 16B units
    const unsigned base0 = (unsigned)((r.y + y0) * IMG_W + r.x) * 256u;
    const unsigned base1 = (unsigned)((r.y + y1) * IMG_W + r.x) * 256u;

    ulonglong2* optr = (ulonglong2*)out + ((size_t)bid * POOL) * 256;

    #pragma unroll
    for (int px = 0; px < POOL; ++px) {
        const float sx = (float)px * stepx;
        const int   x0 = (int)sx;
        const float fx = sx - (float)x0;
        const int   x1 = min(x0 + 1, wm1);

        const unsigned o00 = base0 + (unsigned)x0 * 256u;
        const unsigned o01 = base0 + (unsigned)x1 * 256u;
        const unsigned o10 = base1 + (unsigned)x0 * 256u;
        const unsigned o11 = base1 + (unsigned)x1 * 256u;

        // 8 independent 16B loads, issued back-to-back for MLP.
        const ulonglong2 a00 = __ldg(ibase + o00 + c0);
        const ulonglong2 a01 = __ldg(ibase + o01 + c0);
        const ulonglong2 a10 = __ldg(ibase + o10 + c0);
        const ulonglong2 a11 = __ldg(ibase + o11 + c0);
        const ulonglong2 b00 = __ldg(ibase + o00 + c1);
        const ulonglong2 b01 = __ldg(ibase + o01 + c1);
        const ulonglong2 b10 = __ldg(ibase + o10 + c1);
        const ulonglong2 b11 = __ldg(ibase + o11 + c1);

        // Bilinear weights, packed (splat) into b64 once per cell.
        const float w11 = fx * fy;
        const float w01 = fx - w11;          // fx*(1-fy)
        const float w10 = fy - w11;          // (1-fx)*fy
        const float w00 = 1.0f - fx - w10;   // (1-fx)*(1-fy)
        const unsigned long long W00 = pk(w00, w00);
        const unsigned long long W01 = pk(w01, w01);
        const unsigned long long W10 = pk(w10, w10);
        const unsigned long long W11 = pk(w11, w11);

        optr[c0] = blend2(a00, a01, a10, a11, W00, W01, W10, W11);
        optr[c1] = blend2(b00, b01, b10, b11, W00, W01, W10, W11);
        optr += 256;
    }
}

extern "C" void kernel_launch(void* const* d_in, const int* in_sizes, int n_in,
                              void* d_out, int out_size)
{
    const float* img  = (const float*)d_in[0];
    const int*   rois = (const int*)d_in[1];
    float*       out  = (float*)d_out;

    const int grid = NROIS * POOL;        // 3584 CTAs, one per (roi, py)
    roi_pool_kernel<<<grid, 128>>>(img, rois, out);
}

// round 7
// speedup vs baseline: 1.5642x; 1.0714x over previous
#include <cuda_runtime.h>
#include <cuda_bf16.h>

// img : (1, 64, 64, 1024) float32, NHWC
// rois: (1, 512, 4) int32  -> (x, y, w, h)
// out : (1, 512, 7, 7, 1024) float32
#define POOL   7
#define NROIS  512
#define IMG_W  64

// ---- packed f32x2 helpers (sm_103a) ----
__device__ __forceinline__ unsigned long long pk(float v) {
    unsigned long long r;
    asm("mov.b64 %0, {%1, %1};" : "=l"(r) : "f"(v));
    return r;
}
__device__ __forceinline__ unsigned long long mul2(unsigned long long a, unsigned long long b) {
    unsigned long long r;
    asm("mul.rn.f32x2 %0, %1, %2;" : "=l"(r) : "l"(a), "l"(b));
    return r;
}
__device__ __forceinline__ unsigned long long fma2(unsigned long long a, unsigned long long b,
                                                   unsigned long long c) {
    unsigned long long r;
    asm("fma.rn.f32x2 %0, %1, %2, %3;" : "=l"(r) : "l"(a), "l"(b), "l"(c));
    return r;
}

// 16B img load, non-coherent path, keep line resident in L1 (reused across px).
__device__ __forceinline__ ulonglong2 ldg_el(const ulonglong2* p) {
    ulonglong2 v;
    asm("ld.global.nc.L1::evict_last.v2.b64 {%0, %1}, [%2];"
        : "=l"(v.x), "=l"(v.y) : "l"(p));
    return v;
}
// 16B streaming store (output never re-read) — don't pollute L1.
__device__ __forceinline__ void stg_cs(ulonglong2* p, ulonglong2 v) {
    asm volatile("st.global.cs.v2.b64 [%0], {%1, %2};"
                 :: "l"(p), "l"(v.x), "l"(v.y) : "memory");
}

__device__ __forceinline__ ulonglong2 blend2(ulonglong2 v00, ulonglong2 v01,
                                             ulonglong2 v10, ulonglong2 v11,
                                             float fx, float fy) {
    const float w11 = fx * fy;
    const float w01 = fx - w11;          // fx*(1-fy)
    const float w10 = fy - w11;          // (1-fx)*fy
    const float w00 = 1.0f - fx - w10;   // (1-fx)*(1-fy)
    const unsigned long long W00 = pk(w00), W01 = pk(w01),
                             W10 = pk(w10), W11 = pk(w11);
    ulonglong2 o;
    o.x = fma2(v11.x, W11, fma2(v10.x, W10, fma2(v01.x, W01, mul2(v00.x, W00))));
    o.y = fma2(v11.y, W11, fma2(v10.y, W10, fma2(v01.y, W01, mul2(v00.y, W00))));
    return o;
}

// One CTA per (roi, py) output row: 7 px cells, 256 threads, 1 float4 lane
// each. Depth-1 software pipeline over px (8 independent 16B loads in flight
// per thread), bilinear in packed f32x2, img loads pinned in L1.
__global__ __launch_bounds__(256)
void roi_pool_kernel(const float* __restrict__ img,
                     const int*   __restrict__ rois,
                     float*       __restrict__ out)
{
    const int bid = blockIdx.x;           // roi*7 + py
    const int roi = bid / POOL;
    const int py  = bid - roi * POOL;

    const int4 r = __ldg(((const int4*)rois) + roi);   // x, y, w, h

    // Loop-invariant y-axis work (match reference fp32 arithmetic exactly)
    const float stepx = (float)r.z / (float)POOL;
    const float sy = (float)py * ((float)r.w / (float)POOL);
    const int   y0 = (int)sy;
    const float fy = sy - (float)y0;
    const int   y1 = min(y0 + 1, r.w - 1);
    const int   wm1 = r.z - 1;

    const int c = threadIdx.x;            // 0..255 float4 lane
    const ulonglong2* ibase = (const ulonglong2*)img;
    const unsigned row0 = (unsigned)((r.y + y0) * IMG_W + r.x) * 256u + c;
    const unsigned row1 = (unsigned)((r.y + y1) * IMG_W + r.x) * 256u + c;

    ulonglong2* optr = (ulonglong2*)out + ((size_t)bid * POOL) * 256 + c;

    // ---- prologue: px = 0 (sx = 0, x0 = 0, fx = 0) ----
    float fxc = 0.0f;
    {
        const unsigned x1u = (unsigned)min(1, wm1) * 256u;
        ulonglong2 a00 = ldg_el(ibase + row0);
        ulonglong2 a01 = ldg_el(ibase + row0 + x1u);
        ulonglong2 a10 = ldg_el(ibase + row1);
        ulonglong2 a11 = ldg_el(ibase + row1 + x1u);

        #pragma unroll
        for (int px = 1; px < POOL; ++px) {
            const float sx  = (float)px * stepx;
            const int   x0  = (int)sx;
            const float fxn = sx - (float)x0;
            const unsigned x0u = (unsigned)x0 * 256u;
            const unsigned x1u2 = (unsigned)min(x0 + 1, wm1) * 256u;

            // prefetch next cell's four pixels before consuming current regs
            const ulonglong2 b00 = ldg_el(ibase + row0 + x0u);
            const ulonglong2 b01 = ldg_el(ibase + row0 + x1u2);
            const ulonglong2 b10 = ldg_el(ibase + row1 + x0u);
            const ulonglong2 b11 = ldg_el(ibase + row1 + x1u2);

            stg_cs(optr, blend2(a00, a01, a10, a11, fxc, fy));
            optr += 256;

            a00 = b00; a01 = b01; a10 = b10; a11 = b11;
            fxc = fxn;
        }

        // ---- epilogue: px = 6 ----
        stg_cs(optr, blend2(a00, a01, a10, a11, fxc, fy));
    }
}

extern "C" void kernel_launch(void* const* d_in, const int* in_sizes, int n_in,
                              void* d_out, int out_size)
{
    const float* img  = (const float*)d_in[0];
    const int*   rois = (const int*)d_in[1];
    float*       out  = (float*)d_out;

    const int grid = NROIS * POOL;        // 3584 CTAs, one per (roi, py)
    roi_pool_kernel<<<grid, 256>>>(img, rois, out);
}